// round 4
// baseline (speedup 1.0000x reference)
#include <cuda_runtime.h>
#include <cuda_fp16.h>
#include <cstdint>

// Problem constants (fixed shapes)
#define NN 50000      // nodes
#define EE 1600000    // edges
#define TT 6          // time steps
#define NB 8          // batch
#define NH 16         // hidden

#define GRID 592      // 4 blocks/SM x 148 SMs -> all co-resident
#define NTH  256
#define STRIDE (GRID * NTH)

// Scratch (device globals — no allocation allowed)
__device__ int          g_deg[NN];
__device__ float        g_dinv[NN];
__device__ float4       g_xt[NN * 2];    // x[b, T-1, n] transposed to [n][8] (fp32)
__device__ uint4        g_gth[NN];       // dinv[n] * xt[n][b], packed 8 x f16
__device__ uint4        g_acch[NN];      // scatter accumulator, 8 x f16 per node
__device__ float        g_bsum[NB * NH]; // per-(b,h) node sums
__device__ unsigned int g_cnt;
__device__ unsigned int g_bar;           // grid barrier (cumulative; reset by last block)

// ---------------------------------------------------------------------------
__device__ __forceinline__ float tanh_fast(float x) {
    float y;
    asm("tanh.approx.f32 %0, %1;" : "=f"(y) : "f"(x));
    return y;
}

__device__ __forceinline__ void red_add_v4h2(uint4* addr, uint4 v) {
    asm volatile("red.global.add.noftz.v4.f16x2 [%0], {%1, %2, %3, %4};"
                 :: "l"(addr), "r"(v.x), "r"(v.y), "r"(v.z), "r"(v.w)
                 : "memory");
}

// Software grid sync: cumulative target = phase * GRID. All blocks co-resident
// by construction (launch_bounds occupancy), so spinning is deadlock-free.
__device__ __forceinline__ void grid_sync(unsigned int target) {
    __threadfence();
    __syncthreads();
    if (threadIdx.x == 0) {
        atomicAdd(&g_bar, 1u);
        while (*(volatile unsigned int*)&g_bar < target) {
            __nanosleep(32);
        }
    }
    __syncthreads();
}

// ---------------------------------------------------------------------------
__global__ void __launch_bounds__(NTH, 4)
k_fused(const int* __restrict__ ei, const float* __restrict__ x,
        const float* __restrict__ wxz, const float* __restrict__ bxz,
        const float* __restrict__ bhz, const float* __restrict__ wxh,
        const float* __restrict__ bxh, const float* __restrict__ bhh,
        const float* __restrict__ wlin, const float* __restrict__ blin,
        float* __restrict__ out) {
    const int t   = threadIdx.x;
    const int tid = blockIdx.x * NTH + t;

    // ---------------- P0: zero scratch ----------------
    {
        uint4 z4 = make_uint4(0u, 0u, 0u, 0u);
        for (int j = tid; j < NN; j += STRIDE) {
            g_deg[j]  = 0;
            g_acch[j] = z4;
        }
        if (tid < NB * NH) g_bsum[tid] = 0.f;
    }
    grid_sync(1u * GRID);

    // ---------------- P1: degree histogram + x transpose ----------------
    {
        const int4* s4 = (const int4*)ei;  // src column
        for (int j = tid; j < EE / 4; j += STRIDE) {
            int4 s = __ldcs(&s4[j]);
            atomicAdd(&g_deg[s.x], 1);
            atomicAdd(&g_deg[s.y], 1);
            atomicAdd(&g_deg[s.z], 1);
            atomicAdd(&g_deg[s.w], 1);
        }
        const float* xl = x + (TT - 1) * NN;  // t = T-1 slice, per batch
        for (int n = tid; n < NN; n += STRIDE) {
            float v0 = xl[0 * TT * NN + n];
            float v1 = xl[1 * TT * NN + n];
            float v2 = xl[2 * TT * NN + n];
            float v3 = xl[3 * TT * NN + n];
            float v4 = xl[4 * TT * NN + n];
            float v5 = xl[5 * TT * NN + n];
            float v6 = xl[6 * TT * NN + n];
            float v7 = xl[7 * TT * NN + n];
            g_xt[2 * n]     = make_float4(v0, v1, v2, v3);
            g_xt[2 * n + 1] = make_float4(v4, v5, v6, v7);
        }
    }
    grid_sync(2u * GRID);

    // ---------------- P2: dinv + f16 pack ----------------
    {
        for (int n = tid; n < NN; n += STRIDE) {
            int d = g_deg[n];
            float dv = (d > 0) ? rsqrtf((float)d) : 0.f;
            g_dinv[n] = dv;
            float4 a = g_xt[2 * n];
            float4 b = g_xt[2 * n + 1];
            __half2 h0 = __floats2half2_rn(a.x * dv, a.y * dv);
            __half2 h1 = __floats2half2_rn(a.z * dv, a.w * dv);
            __half2 h2 = __floats2half2_rn(b.x * dv, b.y * dv);
            __half2 h3 = __floats2half2_rn(b.z * dv, b.w * dv);
            uint4 p;
            p.x = *(unsigned int*)&h0;
            p.y = *(unsigned int*)&h1;
            p.z = *(unsigned int*)&h2;
            p.w = *(unsigned int*)&h3;
            g_gth[n] = p;
        }
    }
    grid_sync(3u * GRID);

    // ---------------- P3: edge scatter ----------------
    {
        const int4* s4 = (const int4*)ei;         // src
        const int4* d4 = (const int4*)(ei + EE);  // dst
        for (int j = tid; j < EE / 4; j += STRIDE) {
            int4 s = __ldcs(&s4[j]);
            int4 d = __ldcs(&d4[j]);
            uint4 a0 = __ldg(&g_gth[s.x]);
            uint4 a1 = __ldg(&g_gth[s.y]);
            uint4 a2 = __ldg(&g_gth[s.z]);
            uint4 a3 = __ldg(&g_gth[s.w]);
            red_add_v4h2(&g_acch[d.x], a0);
            red_add_v4h2(&g_acch[d.y], a1);
            red_add_v4h2(&g_acch[d.z], a2);
            red_add_v4h2(&g_acch[d.w], a3);
        }
    }
    grid_sync(4u * GRID);

    // ---------------- P4: gate math + reduction + head ----------------
    __shared__ float sw0z[NH], sw1z[NH], sbz[NH], sw0h[NH], sw1h[NH], sbh[NH];
    if (t < NH) {
        sw0z[t] = wxz[t];  sw1z[t] = wxz[NH + t];  sbz[t] = bxz[t] + bhz[t];
        sw0h[t] = wxh[t];  sw1h[t] = wxh[NH + t];  sbh[t] = bxh[t] + bhh[t];
    }
    __syncthreads();

    float accv[NH];
#pragma unroll
    for (int h = 0; h < NH; h++) accv[h] = 0.f;

    const float*  xt = (const float*)g_xt;
    const __half* ac = (const __half*)g_acch;

    for (int idx = tid; idx < NN * NB; idx += STRIDE) {  // STRIDE % 8 == 0
        int n = idx >> 3;
        float xv  = xt[idx];
        float lxv = -g_dinv[n] * __half2float(ac[idx]);
#pragma unroll
        for (int h = 0; h < NH; h++) {
            float za = fmaf(xv, sw0z[h], fmaf(lxv, sw1z[h], sbz[h]));
            float ha = fmaf(xv, sw0h[h], fmaf(lxv, sw1h[h], sbh[h]));
            float one_m_z = fmaf(-0.5f, tanh_fast(0.5f * za), 0.5f);  // 1 - sigmoid(za)
            float ht = tanh_fast(ha);
            accv[h] += one_m_z * ht;
        }
    }

    // warp reduce: lanes with equal (lane & 7) share batch b
#pragma unroll
    for (int h = 0; h < NH; h++) {
        accv[h] += __shfl_xor_sync(0xffffffffu, accv[h], 8);
        accv[h] += __shfl_xor_sync(0xffffffffu, accv[h], 16);
    }

    __shared__ float sred[8][NB * NH];
    int warp = t >> 5, lane = t & 31;
    if (lane < NB) {
#pragma unroll
        for (int h = 0; h < NH; h++) sred[warp][lane * NH + h] = accv[h];
    }
    __syncthreads();

    if (t < NB * NH) {
        float s = 0.f;
#pragma unroll
        for (int w = 0; w < 8; w++) s += sred[w][t];
        atomicAdd(&g_bsum[t], s);
        __threadfence();
    }
    __syncthreads();

    __shared__ unsigned int s_last;
    if (t == 0) {
        __threadfence();
        s_last = (atomicAdd(&g_cnt, 1u) == gridDim.x - 1) ? 1u : 0u;
    }
    __syncthreads();

    if (s_last) {
        if (t == 0) {          // reset for next graph replay (no one spins anymore)
            g_cnt = 0u;
            g_bar = 0u;
        }
        if (t < NB) {
            const float inv_n = 1.f / (float)NN;
            float s = 0.f;
#pragma unroll
            for (int h = 0; h < NH; h++) {
                float m = __ldcg(&g_bsum[t * NH + h]) * inv_n;
                s += fmaxf(m, 0.f) * wlin[h];
            }
            out[t] = s + blin[0];
        }
    }
}

// ---------------------------------------------------------------------------
extern "C" void kernel_launch(void* const* d_in, const int* in_sizes, int n_in,
                              void* d_out, int out_size) {
    const float* x    = (const float*)d_in[0];  // [B,T,N,1]
    const int*   ei   = (const int*)d_in[1];    // [2,E]
    const float* wxz  = (const float*)d_in[2];  // [2,16]
    const float* bxz  = (const float*)d_in[3];
    const float* bhz  = (const float*)d_in[4];
    const float* wxh  = (const float*)d_in[5];
    const float* bxh  = (const float*)d_in[6];
    const float* bhh  = (const float*)d_in[7];
    const float* wlin = (const float*)d_in[8];  // [1,16]
    const float* blin = (const float*)d_in[9];  // [1]
    float* out = (float*)d_out;                 // [8]

    k_fused<<<GRID, NTH>>>(ei, x, wxz, bxz, bhz, wxh, bxh, bhh, wlin, blin, out);
}

// round 5
// speedup vs baseline: 1.0005x; 1.0005x over previous
#include <cuda_runtime.h>
#include <cuda_fp16.h>
#include <cstdint>

// Problem constants (fixed shapes)
#define NN 50000      // nodes
#define EE 1600000    // edges
#define TT 6          // time steps
#define NB 8          // batch
#define NH 16         // hidden

#define GRID 1184     // 8 blocks/SM x 148 SMs -> all co-resident at 2048 thr/SM
#define NTH  256
#define STRIDE (GRID * NTH)

// Scratch (device globals — no allocation allowed)
__device__ int          g_deg[NN];
__device__ float        g_dinv[NN];
__device__ float4       g_xt[NN * 2];    // x[b, T-1, n] transposed to [n][8] (fp32)
__device__ uint4        g_gth[NN];       // dinv[n] * xt[n][b], packed 8 x f16
__device__ uint4        g_acch[NN];      // scatter accumulator, 8 x f16 per node
__device__ float        g_bsum[NB * NH]; // per-(b,h) node sums
__device__ unsigned int g_cnt;           // combine completion counter
__device__ unsigned int g_bar;           // grid barrier (reset by combine's last block)

// ---------------------------------------------------------------------------
__device__ __forceinline__ float tanh_fast(float x) {
    float y;
    asm("tanh.approx.f32 %0, %1;" : "=f"(y) : "f"(x));
    return y;
}

__device__ __forceinline__ void red_add_v4h2(uint4* addr, uint4 v) {
    asm volatile("red.global.add.noftz.v4.f16x2 [%0], {%1, %2, %3, %4};"
                 :: "l"(addr), "r"(v.x), "r"(v.y), "r"(v.z), "r"(v.w)
                 : "memory");
}

// Software grid sync with cumulative target (all blocks co-resident by
// occupancy construction: 8 blocks/SM, 32-reg budget).
__device__ __forceinline__ void grid_sync(unsigned int target) {
    __threadfence();
    __syncthreads();
    if (threadIdx.x == 0) {
        atomicAdd(&g_bar, 1u);
        while (*(volatile unsigned int*)&g_bar < target) {
            __nanosleep(32);
        }
    }
    __syncthreads();
}

// ---------------------------------------------------------------------------
// K1: zero -> deg+transpose -> dinv+pack -> scatter  (32-reg phases only)
__global__ void __launch_bounds__(NTH, 8)
k_front(const int* __restrict__ ei, const float* __restrict__ x) {
    const int tid = blockIdx.x * NTH + threadIdx.x;

    // ---------------- P0: zero scratch ----------------
    {
        uint4 z4 = make_uint4(0u, 0u, 0u, 0u);
        for (int j = tid; j < NN; j += STRIDE) {
            g_deg[j]  = 0;
            g_acch[j] = z4;
        }
        if (tid < NB * NH) g_bsum[tid] = 0.f;
    }
    grid_sync(1u * GRID);

    // ---------------- P1: degree histogram + x transpose ----------------
    {
        const int4* s4 = (const int4*)ei;  // src column (default caching: warm L2 for P3)
        for (int j = tid; j < EE / 4; j += STRIDE) {
            int4 s = s4[j];
            atomicAdd(&g_deg[s.x], 1);
            atomicAdd(&g_deg[s.y], 1);
            atomicAdd(&g_deg[s.z], 1);
            atomicAdd(&g_deg[s.w], 1);
        }
        const float* xl = x + (TT - 1) * NN;  // t = T-1 slice, per batch
        for (int n = tid; n < NN; n += STRIDE) {
            float4 a, b;
            a.x = xl[0 * TT * NN + n];
            a.y = xl[1 * TT * NN + n];
            a.z = xl[2 * TT * NN + n];
            a.w = xl[3 * TT * NN + n];
            g_xt[2 * n] = a;
            b.x = xl[4 * TT * NN + n];
            b.y = xl[5 * TT * NN + n];
            b.z = xl[6 * TT * NN + n];
            b.w = xl[7 * TT * NN + n];
            g_xt[2 * n + 1] = b;
        }
    }
    grid_sync(2u * GRID);

    // ---------------- P2: dinv + f16 pack ----------------
    {
        for (int n = tid; n < NN; n += STRIDE) {
            int d = g_deg[n];
            float dv = (d > 0) ? rsqrtf((float)d) : 0.f;
            g_dinv[n] = dv;
            float4 a = g_xt[2 * n];
            float4 b = g_xt[2 * n + 1];
            __half2 h0 = __floats2half2_rn(a.x * dv, a.y * dv);
            __half2 h1 = __floats2half2_rn(a.z * dv, a.w * dv);
            __half2 h2 = __floats2half2_rn(b.x * dv, b.y * dv);
            __half2 h3 = __floats2half2_rn(b.z * dv, b.w * dv);
            uint4 p;
            p.x = *(unsigned int*)&h0;
            p.y = *(unsigned int*)&h1;
            p.z = *(unsigned int*)&h2;
            p.w = *(unsigned int*)&h3;
            g_gth[n] = p;
        }
    }
    grid_sync(3u * GRID);

    // ---------------- P3: edge scatter (full 303K-thread parallelism) ----------------
    {
        const int4* s4 = (const int4*)ei;         // src (L2-warm from P1)
        const int4* d4 = (const int4*)(ei + EE);  // dst
        for (int j = tid; j < EE / 4; j += STRIDE) {
            int4 s = __ldg(&s4[j]);
            int4 d = __ldg(&d4[j]);
            uint4 a0 = __ldg(&g_gth[s.x]);
            uint4 a1 = __ldg(&g_gth[s.y]);
            uint4 a2 = __ldg(&g_gth[s.z]);
            uint4 a3 = __ldg(&g_gth[s.w]);
            red_add_v4h2(&g_acch[d.x], a0);
            red_add_v4h2(&g_acch[d.y], a1);
            red_add_v4h2(&g_acch[d.z], a2);
            red_add_v4h2(&g_acch[d.w], a3);
        }
    }
}

// ---------------------------------------------------------------------------
// K2: gate math + reduction over nodes + final linear head (last-block trick)
__global__ void k_combine(const float* __restrict__ wxz, const float* __restrict__ bxz,
                          const float* __restrict__ bhz, const float* __restrict__ wxh,
                          const float* __restrict__ bxh, const float* __restrict__ bhh,
                          const float* __restrict__ wlin, const float* __restrict__ blin,
                          float* __restrict__ out) {
    __shared__ float sw0z[NH], sw1z[NH], sbz[NH], sw0h[NH], sw1h[NH], sbh[NH];
    int t = threadIdx.x;
    if (t < NH) {
        sw0z[t] = wxz[t];  sw1z[t] = wxz[NH + t];  sbz[t] = bxz[t] + bhz[t];
        sw0h[t] = wxh[t];  sw1h[t] = wxh[NH + t];  sbh[t] = bxh[t] + bhh[t];
    }
    __syncthreads();

    float accv[NH];
#pragma unroll
    for (int h = 0; h < NH; h++) accv[h] = 0.f;

    const float*  xt = (const float*)g_xt;
    const __half* ac = (const __half*)g_acch;

    int i = blockIdx.x * blockDim.x + t;
    int stride = gridDim.x * blockDim.x;  // multiple of 8 -> b = i & 7 fixed per thread
    for (int idx = i; idx < NN * NB; idx += stride) {
        int n = idx >> 3;
        float xv  = xt[idx];
        float lxv = -g_dinv[n] * __half2float(ac[idx]);
#pragma unroll
        for (int h = 0; h < NH; h++) {
            float za = fmaf(xv, sw0z[h], fmaf(lxv, sw1z[h], sbz[h]));
            float ha = fmaf(xv, sw0h[h], fmaf(lxv, sw1h[h], sbh[h]));
            float one_m_z = fmaf(-0.5f, tanh_fast(0.5f * za), 0.5f);  // 1 - sigmoid(za)
            float ht = tanh_fast(ha);
            accv[h] += one_m_z * ht;
        }
    }

    // warp reduce: lanes with equal (lane & 7) share batch b
#pragma unroll
    for (int h = 0; h < NH; h++) {
        accv[h] += __shfl_xor_sync(0xffffffffu, accv[h], 8);
        accv[h] += __shfl_xor_sync(0xffffffffu, accv[h], 16);
    }

    __shared__ float sred[8][NB * NH];
    int warp = t >> 5, lane = t & 31;
    if (lane < NB) {
#pragma unroll
        for (int h = 0; h < NH; h++) sred[warp][lane * NH + h] = accv[h];
    }
    __syncthreads();

    if (t < NB * NH) {
        float s = 0.f;
#pragma unroll
        for (int w = 0; w < 8; w++) s += sred[w][t];
        atomicAdd(&g_bsum[t], s);
        __threadfence();
    }
    __syncthreads();

    __shared__ unsigned int s_last;
    if (t == 0) {
        __threadfence();
        s_last = (atomicAdd(&g_cnt, 1u) == gridDim.x - 1) ? 1u : 0u;
    }
    __syncthreads();

    if (s_last) {
        if (t == 0) {          // reset barrier + counter for next graph replay
            g_cnt = 0u;
            g_bar = 0u;
        }
        if (t < NB) {
            const float inv_n = 1.f / (float)NN;
            float s = 0.f;
#pragma unroll
            for (int h = 0; h < NH; h++) {
                float m = __ldcg(&g_bsum[t * NH + h]) * inv_n;
                s += fmaxf(m, 0.f) * wlin[h];
            }
            out[t] = s + blin[0];
        }
    }
}

// ---------------------------------------------------------------------------
extern "C" void kernel_launch(void* const* d_in, const int* in_sizes, int n_in,
                              void* d_out, int out_size) {
    const float* x    = (const float*)d_in[0];  // [B,T,N,1]
    const int*   ei   = (const int*)d_in[1];    // [2,E]
    const float* wxz  = (const float*)d_in[2];  // [2,16]
    const float* bxz  = (const float*)d_in[3];
    const float* bhz  = (const float*)d_in[4];
    const float* wxh  = (const float*)d_in[5];
    const float* bxh  = (const float*)d_in[6];
    const float* bhh  = (const float*)d_in[7];
    const float* wlin = (const float*)d_in[8];  // [1,16]
    const float* blin = (const float*)d_in[9];  // [1]
    float* out = (float*)d_out;                 // [8]

    k_front<<<GRID, NTH>>>(ei, x);
    k_combine<<<592, 256>>>(wxz, bxz, bhz, wxh, bxh, bhh, wlin, blin, out);
}

// round 6
// speedup vs baseline: 1.2341x; 1.2335x over previous
#include <cuda_runtime.h>
#include <cuda_fp16.h>
#include <cstdint>

// Problem constants (fixed shapes)
#define NN 50000      // nodes
#define EE 1600000    // edges
#define TT 6          // time steps
#define NB 8          // batch
#define NH 16         // hidden

// Scratch (device globals — no allocation allowed)
__device__ int          g_deg[NN];
__device__ float        g_dinv[NN];
__device__ float4       g_xt[NN * 2];    // x[b, T-1, n] transposed to [n][8] (fp32)
__device__ uint4        g_gth[NN];       // dinv[n] * xt[n][b], packed 8 x f16
__device__ uint4        g_acch[NN];      // scatter accumulator, 8 x f16 per node
__device__ float        g_bsum[NB * NH]; // per-(b,h) node sums
__device__ unsigned int g_cnt;

// ---------------------------------------------------------------------------
__device__ __forceinline__ float tanh_fast(float x) {
    float y;
    asm("tanh.approx.f32 %0, %1;" : "=f"(y) : "f"(x));
    return y;
}

__device__ __forceinline__ void red_add_v4h2(uint4* addr, uint4 v) {
    asm volatile("red.global.add.noftz.v4.f16x2 [%0], {%1, %2, %3, %4};"
                 :: "l"(addr), "r"(v.x), "r"(v.y), "r"(v.z), "r"(v.w)
                 : "memory");
}

// ---------------------------------------------------------------------------
// K0: zero scratch
__global__ void k_zero() {
    int i = blockIdx.x * blockDim.x + threadIdx.x;
    int stride = gridDim.x * blockDim.x;
    uint4 z4 = make_uint4(0u, 0u, 0u, 0u);
    for (int j = i; j < NN; j += stride) {
        g_deg[j] = 0;
        g_acch[j] = z4;
    }
    if (i < NB * NH) g_bsum[i] = 0.f;
    if (i == 0) g_cnt = 0u;
}

// ---------------------------------------------------------------------------
// K1: degree histogram (src column) + transpose last-timestep x to [n][8]
__global__ void k_deg_xt(const int* __restrict__ ei, const float* __restrict__ x) {
    int i = blockIdx.x * blockDim.x + threadIdx.x;
    int stride = gridDim.x * blockDim.x;

    const int4* s4 = (const int4*)ei;  // src = ei[0..EE)
    for (int j = i; j < EE / 4; j += stride) {
        int4 s = s4[j];
        atomicAdd(&g_deg[s.x], 1);
        atomicAdd(&g_deg[s.y], 1);
        atomicAdd(&g_deg[s.z], 1);
        atomicAdd(&g_deg[s.w], 1);
    }

    // x layout: [B, T, N]; take t = T-1 slice for each b
    const float* xl = x + (TT - 1) * NN;
    for (int n = i; n < NN; n += stride) {
        float4 a, b;
        a.x = xl[0 * TT * NN + n];
        a.y = xl[1 * TT * NN + n];
        a.z = xl[2 * TT * NN + n];
        a.w = xl[3 * TT * NN + n];
        g_xt[2 * n] = a;
        b.x = xl[4 * TT * NN + n];
        b.y = xl[5 * TT * NN + n];
        b.z = xl[6 * TT * NN + n];
        b.w = xl[7 * TT * NN + n];
        g_xt[2 * n + 1] = b;
    }
}

// ---------------------------------------------------------------------------
// K2: dinv = rsqrt(deg) (0 if deg==0); gth = f16(dinv * xt)
__global__ void k_dinv() {
    int i = blockIdx.x * blockDim.x + threadIdx.x;
    int stride = gridDim.x * blockDim.x;
    for (int n = i; n < NN; n += stride) {
        int d = g_deg[n];
        float dv = (d > 0) ? rsqrtf((float)d) : 0.f;
        g_dinv[n] = dv;
        float4 a = g_xt[2 * n];
        float4 b = g_xt[2 * n + 1];
        __half2 h0 = __floats2half2_rn(a.x * dv, a.y * dv);
        __half2 h1 = __floats2half2_rn(a.z * dv, a.w * dv);
        __half2 h2 = __floats2half2_rn(b.x * dv, b.y * dv);
        __half2 h3 = __floats2half2_rn(b.z * dv, b.w * dv);
        uint4 p;
        p.x = *(unsigned int*)&h0;
        p.y = *(unsigned int*)&h1;
        p.z = *(unsigned int*)&h2;
        p.w = *(unsigned int*)&h3;
        g_gth[n] = p;
    }
}

// ---------------------------------------------------------------------------
// K3: main edge scatter: acc[dst][0..7] += gt[src][0..7] via one 16B f16x2 RED
__global__ void __launch_bounds__(256, 8)
k_scatter(const int* __restrict__ ei) {
    int i = blockIdx.x * blockDim.x + threadIdx.x;
    int stride = gridDim.x * blockDim.x;
    const int4* s4 = (const int4*)ei;         // src
    const int4* d4 = (const int4*)(ei + EE);  // dst
    for (int j = i; j < EE / 4; j += stride) {
        int4 s = __ldcs(&s4[j]);
        int4 d = __ldcs(&d4[j]);
        uint4 a0 = __ldg(&g_gth[s.x]);
        uint4 a1 = __ldg(&g_gth[s.y]);
        uint4 a2 = __ldg(&g_gth[s.z]);
        uint4 a3 = __ldg(&g_gth[s.w]);
        red_add_v4h2(&g_acch[d.x], a0);
        red_add_v4h2(&g_acch[d.y], a1);
        red_add_v4h2(&g_acch[d.z], a2);
        red_add_v4h2(&g_acch[d.w], a3);
    }
}

// ---------------------------------------------------------------------------
// K4: gate math + reduction. Each thread owns 2 hidden units (low regs, high occ).
// Warp map: slot = lane>>3 (4 idx per warp-iter), hg = lane&7 -> h = 2hg, 2hg+1.
// idx stride = total_warps*4 (multiple of 8) -> b = idx & 7 loop-invariant.
__global__ void __launch_bounds__(256)
k_combine(const float* __restrict__ wxz, const float* __restrict__ bxz,
          const float* __restrict__ bhz, const float* __restrict__ wxh,
          const float* __restrict__ bxh, const float* __restrict__ bhh,
          const float* __restrict__ wlin, const float* __restrict__ blin,
          float* __restrict__ out) {
    const int t    = threadIdx.x;
    const int lane = t & 31;
    const int slot = lane >> 3;            // 0..3
    const int h0   = (lane & 7) * 2;       // this thread's hidden pair
    const int h1   = h0 + 1;

    // Per-thread weights (z-side pre-halved: tanh(za/2) needs u = za/2 directly)
    const float w0z0 = 0.5f * wxz[h0],      w0z1 = 0.5f * wxz[h1];
    const float w1z0 = 0.5f * wxz[NH + h0], w1z1 = 0.5f * wxz[NH + h1];
    const float bz0  = 0.5f * (bxz[h0] + bhz[h0]), bz1 = 0.5f * (bxz[h1] + bhz[h1]);
    const float w0h0 = wxh[h0],       w0h1 = wxh[h1];
    const float w1h0 = wxh[NH + h0],  w1h1 = wxh[NH + h1];
    const float bh0  = bxh[h0] + bhh[h0], bh1 = bxh[h1] + bhh[h1];

    const int warp_g      = (blockIdx.x * blockDim.x + t) >> 5;
    const int total_warps = (gridDim.x * blockDim.x) >> 5;
    const int stride_idx  = total_warps * 4;   // multiple of 8

    const float*  xt = (const float*)g_xt;
    const __half* ac = (const __half*)g_acch;

    float acc0 = 0.f, acc1 = 0.f;
    int b = -1;
    for (int idx = warp_g * 4 + slot; idx < NN * NB; idx += stride_idx) {
        int n = idx >> 3;
        b = idx & 7;  // invariant
        float xv  = xt[idx];                                   // 8-lane broadcast
        float lxv = -g_dinv[n] * __half2float(ac[idx]);
        // h0
        float u0 = fmaf(xv, w0z0, fmaf(lxv, w1z0, bz0));
        float a0 = fmaf(xv, w0h0, fmaf(lxv, w1h0, bh0));
        // h1 (independent chain -> ILP 2 over the MUFU latency)
        float u1 = fmaf(xv, w0z1, fmaf(lxv, w1z1, bz1));
        float a1 = fmaf(xv, w0h1, fmaf(lxv, w1h1, bh1));
        float tz0 = tanh_fast(u0), th0 = tanh_fast(a0);
        float tz1 = tanh_fast(u1), th1 = tanh_fast(a1);
        acc0 += fmaf(-0.5f, tz0, 0.5f) * th0;   // (1 - sigmoid(za)) * tanh(ha)
        acc1 += fmaf(-0.5f, tz1, 0.5f) * th1;
    }

    __shared__ float sbsum[NB * NH];
    if (t < NB * NH) sbsum[t] = 0.f;
    __syncthreads();
    if (b >= 0) {
        atomicAdd(&sbsum[b * NH + h0], acc0);
        atomicAdd(&sbsum[b * NH + h1], acc1);
    }
    __syncthreads();

    if (t < NB * NH) {
        atomicAdd(&g_bsum[t], sbsum[t]);
        __threadfence();
    }
    __syncthreads();

    __shared__ unsigned int s_last;
    if (t == 0) {
        __threadfence();
        s_last = (atomicAdd(&g_cnt, 1u) == gridDim.x - 1) ? 1u : 0u;
    }
    __syncthreads();

    if (s_last && t < NB) {
        const float inv_n = 1.f / (float)NN;
        float s = 0.f;
#pragma unroll
        for (int h = 0; h < NH; h++) {
            float m = __ldcg(&g_bsum[t * NH + h]) * inv_n;
            s += fmaxf(m, 0.f) * wlin[h];
        }
        out[t] = s + blin[0];
    }
}

// ---------------------------------------------------------------------------
extern "C" void kernel_launch(void* const* d_in, const int* in_sizes, int n_in,
                              void* d_out, int out_size) {
    const float* x    = (const float*)d_in[0];  // [B,T,N,1]
    const int*   ei   = (const int*)d_in[1];    // [2,E]
    const float* wxz  = (const float*)d_in[2];  // [2,16]
    const float* bxz  = (const float*)d_in[3];
    const float* bhz  = (const float*)d_in[4];
    const float* wxh  = (const float*)d_in[5];
    const float* bxh  = (const float*)d_in[6];
    const float* bhh  = (const float*)d_in[7];
    const float* wlin = (const float*)d_in[8];  // [1,16]
    const float* blin = (const float*)d_in[9];  // [1]
    float* out = (float*)d_out;                 // [8]

    k_zero<<<296, 256>>>();
    k_deg_xt<<<1184, 256>>>(ei, x);
    k_dinv<<<196, 256>>>();
    k_scatter<<<1184, 256>>>(ei);
    k_combine<<<1184, 256>>>(wxz, bxz, bhz, wxh, bxh, bhh, wlin, blin, out);
}

// round 7
// speedup vs baseline: 1.2378x; 1.0030x over previous
#include <cuda_runtime.h>
#include <cuda_fp16.h>
#include <cstdint>

// Problem constants (fixed shapes)
#define NN 50000      // nodes
#define EE 1600000    // edges
#define TT 6          // time steps
#define NB 8          // batch
#define NH 16         // hidden

// Scratch (device globals — no allocation allowed)
__device__ int          g_deg[NN];
__device__ float        g_dinv[NN];
__device__ float4       g_xt[NN * 2];    // x[b, T-1, n] transposed to [n][8] (fp32)
__device__ uint4        g_gth[NN];       // dinv[n] * xt[n][b], packed 8 x f16
__device__ uint4        g_acch[NN];      // scatter accumulator, 8 x f16 per node
__device__ float        g_bsum[NB * NH]; // per-(b,h) node sums
__device__ unsigned int g_cnt;

// ---------------------------------------------------------------------------
__device__ __forceinline__ float tanh_fast(float x) {
    float y;
    asm("tanh.approx.f32 %0, %1;" : "=f"(y) : "f"(x));
    return y;
}

__device__ __forceinline__ void red_add_v4h2(uint4* addr, uint4 v) {
    asm volatile("red.global.add.noftz.v4.f16x2 [%0], {%1, %2, %3, %4};"
                 :: "l"(addr), "r"(v.x), "r"(v.y), "r"(v.z), "r"(v.w)
                 : "memory");
}

// ---------------------------------------------------------------------------
// K0: zero scratch
__global__ void k_zero() {
    int i = blockIdx.x * blockDim.x + threadIdx.x;
    int stride = gridDim.x * blockDim.x;
    uint4 z4 = make_uint4(0u, 0u, 0u, 0u);
    for (int j = i; j < NN; j += stride) {
        g_deg[j] = 0;
        g_acch[j] = z4;
    }
    if (i < NB * NH) g_bsum[i] = 0.f;
    if (i == 0) g_cnt = 0u;
}

// ---------------------------------------------------------------------------
// K1: degree histogram (src column) + transpose last-timestep x to [n][8]
__global__ void k_deg_xt(const int* __restrict__ ei, const float* __restrict__ x) {
    int i = blockIdx.x * blockDim.x + threadIdx.x;
    int stride = gridDim.x * blockDim.x;

    const int4* s4 = (const int4*)ei;  // src = ei[0..EE)
    for (int j = i; j < EE / 4; j += stride) {
        int4 s = __ldcs(&s4[j]);
        atomicAdd(&g_deg[s.x], 1);
        atomicAdd(&g_deg[s.y], 1);
        atomicAdd(&g_deg[s.z], 1);
        atomicAdd(&g_deg[s.w], 1);
    }

    // x layout: [B, T, N]; take t = T-1 slice for each b
    const float* xl = x + (TT - 1) * NN;
    for (int n = i; n < NN; n += stride) {
        float4 a, b;
        a.x = xl[0 * TT * NN + n];
        a.y = xl[1 * TT * NN + n];
        a.z = xl[2 * TT * NN + n];
        a.w = xl[3 * TT * NN + n];
        g_xt[2 * n] = a;
        b.x = xl[4 * TT * NN + n];
        b.y = xl[5 * TT * NN + n];
        b.z = xl[6 * TT * NN + n];
        b.w = xl[7 * TT * NN + n];
        g_xt[2 * n + 1] = b;
    }
}

// ---------------------------------------------------------------------------
// K2: dinv = rsqrt(deg) (0 if deg==0); gth = f16(dinv * xt)
__global__ void k_dinv() {
    int i = blockIdx.x * blockDim.x + threadIdx.x;
    int stride = gridDim.x * blockDim.x;
    for (int n = i; n < NN; n += stride) {
        int d = g_deg[n];
        float dv = (d > 0) ? rsqrtf((float)d) : 0.f;
        g_dinv[n] = dv;
        float4 a = g_xt[2 * n];
        float4 b = g_xt[2 * n + 1];
        __half2 h0 = __floats2half2_rn(a.x * dv, a.y * dv);
        __half2 h1 = __floats2half2_rn(a.z * dv, a.w * dv);
        __half2 h2 = __floats2half2_rn(b.x * dv, b.y * dv);
        __half2 h3 = __floats2half2_rn(b.z * dv, b.w * dv);
        uint4 p;
        p.x = *(unsigned int*)&h0;
        p.y = *(unsigned int*)&h1;
        p.z = *(unsigned int*)&h2;
        p.w = *(unsigned int*)&h3;
        g_gth[n] = p;
    }
}

// ---------------------------------------------------------------------------
// K3: main edge scatter: acc[dst][0..7] += gt[src][0..7] via one 16B f16x2 RED
__global__ void __launch_bounds__(256, 8)
k_scatter(const int* __restrict__ ei) {
    int i = blockIdx.x * blockDim.x + threadIdx.x;
    int stride = gridDim.x * blockDim.x;
    const int4* s4 = (const int4*)ei;         // src
    const int4* d4 = (const int4*)(ei + EE);  // dst
    for (int j = i; j < EE / 4; j += stride) {
        int4 s = __ldcs(&s4[j]);
        int4 d = __ldcs(&d4[j]);
        uint4 a0 = __ldg(&g_gth[s.x]);
        uint4 a1 = __ldg(&g_gth[s.y]);
        uint4 a2 = __ldg(&g_gth[s.z]);
        uint4 a3 = __ldg(&g_gth[s.w]);
        red_add_v4h2(&g_acch[d.x], a0);
        red_add_v4h2(&g_acch[d.y], a1);
        red_add_v4h2(&g_acch[d.z], a2);
        red_add_v4h2(&g_acch[d.w], a3);
    }
}

// ---------------------------------------------------------------------------
// K4: gate math + reduction. Each thread owns 2 hidden units (low regs, high occ).
// Weights staged through smem ONCE PER BLOCK to avoid the L2 parameter-sector
// hotspot of per-thread global loads.
// Warp map: slot = lane>>3 (4 idx per warp-iter), hg = lane&7 -> h = 2hg, 2hg+1.
// idx stride = total_warps*4 (multiple of 8) -> b = idx & 7 loop-invariant.
__global__ void __launch_bounds__(256)
k_combine(const float* __restrict__ wxz, const float* __restrict__ bxz,
          const float* __restrict__ bhz, const float* __restrict__ wxh,
          const float* __restrict__ bxh, const float* __restrict__ bhh,
          const float* __restrict__ wlin, const float* __restrict__ blin,
          float* __restrict__ out) {
    const int t    = threadIdx.x;
    const int lane = t & 31;
    const int slot = lane >> 3;            // 0..3
    const int h0   = (lane & 7) * 2;       // this thread's hidden pair
    const int h1   = h0 + 1;

    // Stage weights in smem once per block (z-side pre-halved for tanh(za/2))
    __shared__ float swz0[NH], swz1[NH], sbz[NH], swh0[NH], swh1[NH], sbh[NH];
    if (t < NH) {
        swz0[t] = 0.5f * wxz[t];
        swz1[t] = 0.5f * wxz[NH + t];
        sbz[t]  = 0.5f * (bxz[t] + bhz[t]);
        swh0[t] = wxh[t];
        swh1[t] = wxh[NH + t];
        sbh[t]  = bxh[t] + bhh[t];
    }
    __syncthreads();

    const float w0z0 = swz0[h0], w0z1 = swz0[h1];
    const float w1z0 = swz1[h0], w1z1 = swz1[h1];
    const float bz0  = sbz[h0],  bz1  = sbz[h1];
    const float w0h0 = swh0[h0], w0h1 = swh0[h1];
    const float w1h0 = swh1[h0], w1h1 = swh1[h1];
    const float bh0  = sbh[h0],  bh1  = sbh[h1];

    const int warp_g      = (blockIdx.x * blockDim.x + t) >> 5;
    const int total_warps = (gridDim.x * blockDim.x) >> 5;
    const int stride_idx  = total_warps * 4;   // multiple of 8

    const float*  xt = (const float*)g_xt;
    const __half* ac = (const __half*)g_acch;

    float acc0 = 0.f, acc1 = 0.f;
    int b = -1;
    for (int idx = warp_g * 4 + slot; idx < NN * NB; idx += stride_idx) {
        int n = idx >> 3;
        b = idx & 7;  // invariant
        float xv  = xt[idx];                                   // 8-lane broadcast
        float lxv = -g_dinv[n] * __half2float(ac[idx]);
        // h0
        float u0 = fmaf(xv, w0z0, fmaf(lxv, w1z0, bz0));
        float a0 = fmaf(xv, w0h0, fmaf(lxv, w1h0, bh0));
        // h1 (independent chain -> ILP 2 over the MUFU latency)
        float u1 = fmaf(xv, w0z1, fmaf(lxv, w1z1, bz1));
        float a1 = fmaf(xv, w0h1, fmaf(lxv, w1h1, bh1));
        float tz0 = tanh_fast(u0), th0 = tanh_fast(a0);
        float tz1 = tanh_fast(u1), th1 = tanh_fast(a1);
        acc0 += fmaf(-0.5f, tz0, 0.5f) * th0;   // (1 - sigmoid(za)) * tanh(ha)
        acc1 += fmaf(-0.5f, tz1, 0.5f) * th1;
    }

    __shared__ float sbsum[NB * NH];
    if (t < NB * NH) sbsum[t] = 0.f;
    __syncthreads();
    if (b >= 0) {
        atomicAdd(&sbsum[b * NH + h0], acc0);
        atomicAdd(&sbsum[b * NH + h1], acc1);
    }
    __syncthreads();

    if (t < NB * NH) {
        atomicAdd(&g_bsum[t], sbsum[t]);
        __threadfence();
    }
    __syncthreads();

    __shared__ unsigned int s_last;
    if (t == 0) {
        __threadfence();
        s_last = (atomicAdd(&g_cnt, 1u) == gridDim.x - 1) ? 1u : 0u;
    }
    __syncthreads();

    if (s_last && t < NB) {
        const float inv_n = 1.f / (float)NN;
        float s = 0.f;
#pragma unroll
        for (int h = 0; h < NH; h++) {
            float m = __ldcg(&g_bsum[t * NH + h]) * inv_n;
            s += fmaxf(m, 0.f) * wlin[h];
        }
        out[t] = s + blin[0];
    }
}

// ---------------------------------------------------------------------------
extern "C" void kernel_launch(void* const* d_in, const int* in_sizes, int n_in,
                              void* d_out, int out_size) {
    const float* x    = (const float*)d_in[0];  // [B,T,N,1]
    const int*   ei   = (const int*)d_in[1];    // [2,E]
    const float* wxz  = (const float*)d_in[2];  // [2,16]
    const float* bxz  = (const float*)d_in[3];
    const float* bhz  = (const float*)d_in[4];
    const float* wxh  = (const float*)d_in[5];
    const float* bxh  = (const float*)d_in[6];
    const float* bhh  = (const float*)d_in[7];
    const float* wlin = (const float*)d_in[8];  // [1,16]
    const float* blin = (const float*)d_in[9];  // [1]
    float* out = (float*)d_out;                 // [8]

    k_zero<<<296, 256>>>();
    k_deg_xt<<<1184, 256>>>(ei, x);
    k_dinv<<<196, 256>>>();
    k_scatter<<<1184, 256>>>(ei);
    k_combine<<<1184, 256>>>(wxz, bxz, bhz, wxh, bxh, bhh, wlin, blin, out);
}

// round 8
// speedup vs baseline: 1.3879x; 1.1212x over previous
#include <cuda_runtime.h>
#include <cuda_fp16.h>
#include <cstdint>

// Problem constants (fixed shapes)
#define NN 50000      // nodes
#define EE 1600000    // edges
#define TT 6          // time steps
#define NB 8          // batch
#define NH 16         // hidden

// Scratch (device globals — no allocation allowed)
__device__ int          g_deg[NN];
__device__ float        g_dinv[NN];
__device__ float4       g_xt[NN * 2];    // x[b, T-1, n] transposed to [n][8] (fp32)
__device__ uint4        g_gth[NN];       // dinv[n] * xt[n][b], packed 8 x f16
__device__ uint4        g_acch[NN];      // scatter accumulator, 8 x f16 per node
__device__ float        g_bsum[NB * NH]; // per-(b,h) node sums
__device__ unsigned int g_cnt;

// ---------------------------------------------------------------------------
__device__ __forceinline__ float tanh_fast(float x) {
    float y;
    asm("tanh.approx.f32 %0, %1;" : "=f"(y) : "f"(x));
    return y;
}

__device__ __forceinline__ void red_add_v4h2(uint4* addr, uint4 v) {
    asm volatile("red.global.add.noftz.v4.f16x2 [%0], {%1, %2, %3, %4};"
                 :: "l"(addr), "r"(v.x), "r"(v.y), "r"(v.z), "r"(v.w)
                 : "memory");
}

// ---------------------------------------------------------------------------
// K0: zero deg + bsum + cnt (acch is zeroed later, inside k_dinv)
__global__ void k_zero() {
    int i = blockIdx.x * blockDim.x + threadIdx.x;
    int stride = gridDim.x * blockDim.x;
    for (int j = i; j < NN; j += stride) g_deg[j] = 0;
    if (i < NB * NH) g_bsum[i] = 0.f;
    if (i == 0) g_cnt = 0u;
}

// ---------------------------------------------------------------------------
// K1: degree histogram (src column) + transpose last-timestep x to [n][8]
__global__ void k_deg_xt(const int* __restrict__ ei, const float* __restrict__ x) {
    int i = blockIdx.x * blockDim.x + threadIdx.x;
    int stride = gridDim.x * blockDim.x;

    const int4* s4 = (const int4*)ei;  // src = ei[0..EE)
    for (int j = i; j < EE / 4; j += stride) {
        int4 s = __ldcs(&s4[j]);
        atomicAdd(&g_deg[s.x], 1);
        atomicAdd(&g_deg[s.y], 1);
        atomicAdd(&g_deg[s.z], 1);
        atomicAdd(&g_deg[s.w], 1);
    }

    // x layout: [B, T, N]; take t = T-1 slice for each b
    const float* xl = x + (TT - 1) * NN;
    for (int n = i; n < NN; n += stride) {
        float4 a, b;
        a.x = xl[0 * TT * NN + n];
        a.y = xl[1 * TT * NN + n];
        a.z = xl[2 * TT * NN + n];
        a.w = xl[3 * TT * NN + n];
        g_xt[2 * n] = a;
        b.x = xl[4 * TT * NN + n];
        b.y = xl[5 * TT * NN + n];
        b.z = xl[6 * TT * NN + n];
        b.w = xl[7 * TT * NN + n];
        g_xt[2 * n + 1] = b;
    }
}

// ---------------------------------------------------------------------------
// K2: dinv = rsqrt(deg); gth = f16(dinv * xt); also zero acch (feeds scatter next)
__global__ void k_dinv() {
    int i = blockIdx.x * blockDim.x + threadIdx.x;
    int stride = gridDim.x * blockDim.x;
    uint4 z4 = make_uint4(0u, 0u, 0u, 0u);
    for (int n = i; n < NN; n += stride) {
        int d = g_deg[n];
        float dv = (d > 0) ? rsqrtf((float)d) : 0.f;
        g_dinv[n] = dv;
        float4 a = g_xt[2 * n];
        float4 b = g_xt[2 * n + 1];
        __half2 h0 = __floats2half2_rn(a.x * dv, a.y * dv);
        __half2 h1 = __floats2half2_rn(a.z * dv, a.w * dv);
        __half2 h2 = __floats2half2_rn(b.x * dv, b.y * dv);
        __half2 h3 = __floats2half2_rn(b.z * dv, b.w * dv);
        uint4 p;
        p.x = *(unsigned int*)&h0;
        p.y = *(unsigned int*)&h1;
        p.z = *(unsigned int*)&h2;
        p.w = *(unsigned int*)&h3;
        g_gth[n] = p;
        g_acch[n] = z4;
    }
}

// ---------------------------------------------------------------------------
// K3: main edge scatter: acc[dst][0..7] += gt[src][0..7] via one 16B f16x2 RED
__global__ void k_scatter(const int* __restrict__ ei) {
    int i = blockIdx.x * blockDim.x + threadIdx.x;
    int stride = gridDim.x * blockDim.x;
    const int4* s4 = (const int4*)ei;         // src
    const int4* d4 = (const int4*)(ei + EE);  // dst
    for (int j = i; j < EE / 4; j += stride) {
        int4 s = __ldcs(&s4[j]);
        int4 d = __ldcs(&d4[j]);
        uint4 a0 = __ldg(&g_gth[s.x]);
        uint4 a1 = __ldg(&g_gth[s.y]);
        uint4 a2 = __ldg(&g_gth[s.z]);
        uint4 a3 = __ldg(&g_gth[s.w]);
        red_add_v4h2(&g_acch[d.x], a0);
        red_add_v4h2(&g_acch[d.y], a1);
        red_add_v4h2(&g_acch[d.z], a2);
        red_add_v4h2(&g_acch[d.w], a3);
    }
}

// ---------------------------------------------------------------------------
// K4: gate math + reduction. 4 hidden units per thread.
// Warp map: slot = lane>>2 (8 idx per warp-iter), hg = (lane&3)*4 -> h in [hg, hg+4).
// idx stride = total_warps*8 (multiple of 8) -> b = idx & 7 loop-invariant,
// and n = idx>>3 is UNIFORM across the warp (one dinv load).
__global__ void __launch_bounds__(256)
k_combine(const float* __restrict__ wxz, const float* __restrict__ bxz,
          const float* __restrict__ bhz, const float* __restrict__ wxh,
          const float* __restrict__ bxh, const float* __restrict__ bhh,
          const float* __restrict__ wlin, const float* __restrict__ blin,
          float* __restrict__ out) {
    const int t    = threadIdx.x;
    const int lane = t & 31;
    const int slot = lane >> 2;            // 0..7
    const int hg   = (lane & 3) * 4;       // h base: 0,4,8,12

    // Stage weights in smem once per block (z-side pre-halved for tanh(za/2))
    __shared__ float swz0[NH], swz1[NH], sbz[NH], swh0[NH], swh1[NH], sbh[NH];
    if (t < NH) {
        swz0[t] = 0.5f * wxz[t];
        swz1[t] = 0.5f * wxz[NH + t];
        sbz[t]  = 0.5f * (bxz[t] + bhz[t]);
        swh0[t] = wxh[t];
        swh1[t] = wxh[NH + t];
        sbh[t]  = bxh[t] + bhh[t];
    }
    __syncthreads();

    float w0z[4], w1z[4], bz[4], w0h[4], w1h[4], bh[4];
#pragma unroll
    for (int j = 0; j < 4; j++) {
        w0z[j] = swz0[hg + j];  w1z[j] = swz1[hg + j];  bz[j] = sbz[hg + j];
        w0h[j] = swh0[hg + j];  w1h[j] = swh1[hg + j];  bh[j] = sbh[hg + j];
    }

    const int warp_g      = (blockIdx.x * blockDim.x + t) >> 5;
    const int total_warps = (gridDim.x * blockDim.x) >> 5;   // 4736
    const int stride_idx  = total_warps * 8;                 // multiple of 8

    const float*  xt = (const float*)g_xt;
    const __half* ac = (const __half*)g_acch;

    float acc[4] = {0.f, 0.f, 0.f, 0.f};
    int b = -1;
    for (int idx = warp_g * 8 + slot; idx < NN * NB; idx += stride_idx) {
        int n = idx >> 3;                 // uniform across the warp
        b = idx & 7;                      // invariant per thread
        float xv  = xt[idx];              // 4-lane broadcast, 32B/warp
        float lxv = -g_dinv[n] * __half2float(ac[idx]);
#pragma unroll
        for (int j = 0; j < 4; j++) {
            float u = fmaf(xv, w0z[j], fmaf(lxv, w1z[j], bz[j]));
            float a = fmaf(xv, w0h[j], fmaf(lxv, w1h[j], bh[j]));
            // (1 - sigmoid(2u)) * tanh(a) = (0.5 - 0.5*tanh(u)) * tanh(a)
            acc[j] += fmaf(-0.5f, tanh_fast(u), 0.5f) * tanh_fast(a);
        }
    }

    __shared__ float sbsum[NB * NH];
    if (t < NB * NH) sbsum[t] = 0.f;
    __syncthreads();
    if (b >= 0) {
#pragma unroll
        for (int j = 0; j < 4; j++) atomicAdd(&sbsum[b * NH + hg + j], acc[j]);
    }
    __syncthreads();

    if (t < NB * NH) atomicAdd(&g_bsum[t], sbsum[t]);
    __syncthreads();

    __shared__ unsigned int s_last;
    if (t == 0) {
        __threadfence();
        s_last = (atomicAdd(&g_cnt, 1u) == gridDim.x - 1) ? 1u : 0u;
    }
    __syncthreads();

    if (s_last && t < NB) {
        const float inv_n = 1.f / (float)NN;
        float s = 0.f;
#pragma unroll
        for (int h = 0; h < NH; h++) {
            float m = __ldcg(&g_bsum[t * NH + h]) * inv_n;
            s += fmaxf(m, 0.f) * wlin[h];
        }
        out[t] = s + blin[0];
    }
}

// ---------------------------------------------------------------------------
extern "C" void kernel_launch(void* const* d_in, const int* in_sizes, int n_in,
                              void* d_out, int out_size) {
    const float* x    = (const float*)d_in[0];  // [B,T,N,1]
    const int*   ei   = (const int*)d_in[1];    // [2,E]
    const float* wxz  = (const float*)d_in[2];  // [2,16]
    const float* bxz  = (const float*)d_in[3];
    const float* bhz  = (const float*)d_in[4];
    const float* wxh  = (const float*)d_in[5];
    const float* bxh  = (const float*)d_in[6];
    const float* bhh  = (const float*)d_in[7];
    const float* wlin = (const float*)d_in[8];  // [1,16]
    const float* blin = (const float*)d_in[9];  // [1]
    float* out = (float*)d_out;                 // [8]

    k_zero<<<128, 256>>>();
    k_deg_xt<<<1184, 256>>>(ei, x);
    k_dinv<<<296, 256>>>();
    k_scatter<<<1184, 256>>>(ei);
    k_combine<<<592, 256>>>(wxz, bxz, bhz, wxh, bxh, bhh, wlin, blin, out);
}

// round 9
// speedup vs baseline: 1.3963x; 1.0061x over previous
#include <cuda_runtime.h>
#include <cuda_fp16.h>
#include <cstdint>

// Problem constants (fixed shapes)
#define NN 50000      // nodes
#define EE 1600000    // edges
#define TT 6          // time steps
#define NB 8          // batch
#define NH 16         // hidden

// Scratch (device globals — no allocation allowed)
__device__ int          g_deg[NN];
__device__ float        g_dinv[NN];
__device__ float4       g_xt[NN * 2];    // x[b, T-1, n] transposed to [n][8] (fp32)
__device__ uint4        g_gth[NN];       // dinv[n] * xt[n][b], packed 8 x f16
__device__ uint4        g_acch[NN];      // scatter accumulator, 8 x f16 per node
__device__ float        g_bsum[NB * NH]; // per-(b,h) node sums
__device__ unsigned int g_cnt;

// ---------------------------------------------------------------------------
__device__ __forceinline__ __half2 tanh_h2(__half2 x) {
    unsigned int xi = *(unsigned int*)&x;
    unsigned int yi;
    asm("tanh.approx.f16x2 %0, %1;" : "=r"(yi) : "r"(xi));
    return *(__half2*)&yi;
}

__device__ __forceinline__ void red_add_v4h2(uint4* addr, uint4 v) {
    asm volatile("red.global.add.noftz.v4.f16x2 [%0], {%1, %2, %3, %4};"
                 :: "l"(addr), "r"(v.x), "r"(v.y), "r"(v.z), "r"(v.w)
                 : "memory");
}

// ---------------------------------------------------------------------------
// K1: degree histogram (src column) + transpose last-timestep x to [n][8]
__global__ void k_deg_xt(const int* __restrict__ ei, const float* __restrict__ x) {
    int i = blockIdx.x * blockDim.x + threadIdx.x;
    int stride = gridDim.x * blockDim.x;

    const int4* s4 = (const int4*)ei;  // src = ei[0..EE)
    for (int j = i; j < EE / 4; j += stride) {
        int4 s = __ldcs(&s4[j]);
        atomicAdd(&g_deg[s.x], 1);
        atomicAdd(&g_deg[s.y], 1);
        atomicAdd(&g_deg[s.z], 1);
        atomicAdd(&g_deg[s.w], 1);
    }

    // x layout: [B, T, N]; take t = T-1 slice for each b (stride-1 in n -> coalesced)
    const float* xl = x + (TT - 1) * NN;
    for (int n = i; n < NN; n += stride) {
        float4 a, b;
        a.x = xl[0 * TT * NN + n];
        a.y = xl[1 * TT * NN + n];
        a.z = xl[2 * TT * NN + n];
        a.w = xl[3 * TT * NN + n];
        g_xt[2 * n] = a;
        b.x = xl[4 * TT * NN + n];
        b.y = xl[5 * TT * NN + n];
        b.z = xl[6 * TT * NN + n];
        b.w = xl[7 * TT * NN + n];
        g_xt[2 * n + 1] = b;
    }
}

// ---------------------------------------------------------------------------
// K2: dinv = rsqrt(deg); gth = f16(dinv * xt); zero acch + bsum + cnt
__global__ void k_dinv() {
    int i = blockIdx.x * blockDim.x + threadIdx.x;
    int stride = gridDim.x * blockDim.x;
    uint4 z4 = make_uint4(0u, 0u, 0u, 0u);
    for (int n = i; n < NN; n += stride) {
        int d = g_deg[n];
        float dv = (d > 0) ? rsqrtf((float)d) : 0.f;
        g_dinv[n] = dv;
        float4 a = g_xt[2 * n];
        float4 b = g_xt[2 * n + 1];
        __half2 h0 = __floats2half2_rn(a.x * dv, a.y * dv);
        __half2 h1 = __floats2half2_rn(a.z * dv, a.w * dv);
        __half2 h2 = __floats2half2_rn(b.x * dv, b.y * dv);
        __half2 h3 = __floats2half2_rn(b.z * dv, b.w * dv);
        uint4 p;
        p.x = *(unsigned int*)&h0;
        p.y = *(unsigned int*)&h1;
        p.z = *(unsigned int*)&h2;
        p.w = *(unsigned int*)&h3;
        g_gth[n] = p;
        g_acch[n] = z4;
    }
    if (i < NB * NH) g_bsum[i] = 0.f;
    if (i == 0) g_cnt = 0u;
}

// ---------------------------------------------------------------------------
// K3: main edge scatter: acc[dst][0..7] += gt[src][0..7] via one 16B f16x2 RED
__global__ void k_scatter(const int* __restrict__ ei) {
    int i = blockIdx.x * blockDim.x + threadIdx.x;
    int stride = gridDim.x * blockDim.x;
    const int4* s4 = (const int4*)ei;         // src
    const int4* d4 = (const int4*)(ei + EE);  // dst
    for (int j = i; j < EE / 4; j += stride) {
        int4 s = __ldcs(&s4[j]);
        int4 d = __ldcs(&d4[j]);
        uint4 a0 = __ldg(&g_gth[s.x]);
        uint4 a1 = __ldg(&g_gth[s.y]);
        uint4 a2 = __ldg(&g_gth[s.z]);
        uint4 a3 = __ldg(&g_gth[s.w]);
        red_add_v4h2(&g_acch[d.x], a0);
        red_add_v4h2(&g_acch[d.y], a1);
        red_add_v4h2(&g_acch[d.z], a2);
        red_add_v4h2(&g_acch[d.w], a3);
    }
}

// ---------------------------------------------------------------------------
// K4: gate math + reduction. 4 hidden units per thread, f16x2 packed tanh.
// Warp map: slot = lane>>2 -> b = slot (stride multiple of 8); hg = (lane&3)*4.
// n = idx>>3 is uniform across the warp.
__global__ void __launch_bounds__(256)
k_combine(const float* __restrict__ wxz, const float* __restrict__ bxz,
          const float* __restrict__ bhz, const float* __restrict__ wxh,
          const float* __restrict__ bxh, const float* __restrict__ bhh,
          const float* __restrict__ wlin, const float* __restrict__ blin,
          float* __restrict__ out) {
    const int t    = threadIdx.x;
    const int lane = t & 31;
    const int slot = lane >> 2;            // 0..7 == batch b
    const int hg   = (lane & 3) * 4;       // h base: 0,4,8,12

    // Stage weights in smem once per block (z-side pre-halved for tanh(za/2))
    __shared__ float swz0[NH], swz1[NH], sbz[NH], swh0[NH], swh1[NH], sbh[NH];
    if (t < NH) {
        swz0[t] = 0.5f * wxz[t];
        swz1[t] = 0.5f * wxz[NH + t];
        sbz[t]  = 0.5f * (bxz[t] + bhz[t]);
        swh0[t] = wxh[t];
        swh1[t] = wxh[NH + t];
        sbh[t]  = bxh[t] + bhh[t];
    }
    __syncthreads();

    float w0z[4], w1z[4], bz[4], w0h[4], w1h[4], bh[4];
#pragma unroll
    for (int j = 0; j < 4; j++) {
        w0z[j] = swz0[hg + j];  w1z[j] = swz1[hg + j];  bz[j] = sbz[hg + j];
        w0h[j] = swh0[hg + j];  w1h[j] = swh1[hg + j];  bh[j] = sbh[hg + j];
    }

    const int warp_g      = (blockIdx.x * blockDim.x + t) >> 5;
    const int total_warps = (gridDim.x * blockDim.x) >> 5;   // 4736
    const int stride_idx  = total_warps * 8;                 // multiple of 8

    const float*  xt = (const float*)g_xt;
    const __half* ac = (const __half*)g_acch;

    const __half2 c_nh = __float2half2_rn(-0.5f);
    const __half2 c_ph = __float2half2_rn(0.5f);

    __half2 acc01 = __float2half2_rn(0.f);
    __half2 acc23 = __float2half2_rn(0.f);
    int b = -1;
    for (int idx = warp_g * 8 + slot; idx < NN * NB; idx += stride_idx) {
        int n = idx >> 3;                 // uniform across the warp
        b = idx & 7;                      // == slot, invariant
        float xv  = xt[idx];              // 4-lane broadcast, 32B/warp
        float lxv = -g_dinv[n] * __half2float(ac[idx]);

        float u0 = fmaf(xv, w0z[0], fmaf(lxv, w1z[0], bz[0]));
        float u1 = fmaf(xv, w0z[1], fmaf(lxv, w1z[1], bz[1]));
        float u2 = fmaf(xv, w0z[2], fmaf(lxv, w1z[2], bz[2]));
        float u3 = fmaf(xv, w0z[3], fmaf(lxv, w1z[3], bz[3]));
        float a0 = fmaf(xv, w0h[0], fmaf(lxv, w1h[0], bh[0]));
        float a1 = fmaf(xv, w0h[1], fmaf(lxv, w1h[1], bh[1]));
        float a2 = fmaf(xv, w0h[2], fmaf(lxv, w1h[2], bh[2]));
        float a3 = fmaf(xv, w0h[3], fmaf(lxv, w1h[3], bh[3]));

        __half2 tz01 = tanh_h2(__floats2half2_rn(u0, u1));
        __half2 tz23 = tanh_h2(__floats2half2_rn(u2, u3));
        __half2 th01 = tanh_h2(__floats2half2_rn(a0, a1));
        __half2 th23 = tanh_h2(__floats2half2_rn(a2, a3));

        __half2 omz01 = __hfma2(c_nh, tz01, c_ph);  // 0.5 - 0.5*tanh(za/2) = 1 - sigmoid(za)
        __half2 omz23 = __hfma2(c_nh, tz23, c_ph);
        acc01 = __hfma2(omz01, th01, acc01);
        acc23 = __hfma2(omz23, th23, acc23);
    }

    __shared__ float sbsum[NB * NH];
    if (t < NB * NH) sbsum[t] = 0.f;
    __syncthreads();
    if (b >= 0) {
        atomicAdd(&sbsum[b * NH + hg + 0], __low2float(acc01));
        atomicAdd(&sbsum[b * NH + hg + 1], __high2float(acc01));
        atomicAdd(&sbsum[b * NH + hg + 2], __low2float(acc23));
        atomicAdd(&sbsum[b * NH + hg + 3], __high2float(acc23));
    }
    __syncthreads();

    if (t < NB * NH) atomicAdd(&g_bsum[t], sbsum[t]);
    __syncthreads();

    __shared__ unsigned int s_last;
    if (t == 0) {
        __threadfence();
        s_last = (atomicAdd(&g_cnt, 1u) == gridDim.x - 1) ? 1u : 0u;
    }
    __syncthreads();

    if (s_last && t < NB) {
        const float inv_n = 1.f / (float)NN;
        float s = 0.f;
#pragma unroll
        for (int h = 0; h < NH; h++) {
            float m = __ldcg(&g_bsum[t * NH + h]) * inv_n;
            s += fmaxf(m, 0.f) * wlin[h];
        }
        out[t] = s + blin[0];
    }
}

// ---------------------------------------------------------------------------
extern "C" void kernel_launch(void* const* d_in, const int* in_sizes, int n_in,
                              void* d_out, int out_size) {
    const float* x    = (const float*)d_in[0];  // [B,T,N,1]
    const int*   ei   = (const int*)d_in[1];    // [2,E]
    const float* wxz  = (const float*)d_in[2];  // [2,16]
    const float* bxz  = (const float*)d_in[3];
    const float* bhz  = (const float*)d_in[4];
    const float* wxh  = (const float*)d_in[5];
    const float* bxh  = (const float*)d_in[6];
    const float* bhh  = (const float*)d_in[7];
    const float* wlin = (const float*)d_in[8];  // [1,16]
    const float* blin = (const float*)d_in[9];  // [1]
    float* out = (float*)d_out;                 // [8]

    // zero g_deg via a graph memset node (replaces the k_zero kernel)
    void* p_deg = nullptr;
    cudaGetSymbolAddress(&p_deg, g_deg);
    cudaMemsetAsync(p_deg, 0, NN * sizeof(int));

    k_deg_xt<<<1184, 256>>>(ei, x);
    k_dinv<<<296, 256>>>();
    k_scatter<<<1184, 256>>>(ei);
    k_combine<<<592, 256>>>(wxz, bxz, bhz, wxh, bxh, bhh, wlin, blin, out);
}

// round 10
// speedup vs baseline: 1.3992x; 1.0020x over previous
#include <cuda_runtime.h>
#include <cuda_fp16.h>
#include <cstdint>

// Problem constants (fixed shapes)
#define NN 50000      // nodes
#define EE 1600000    // edges
#define TT 6          // time steps
#define NB 8          // batch
#define NH 16         // hidden

// Scratch (device globals — no allocation allowed)
__device__ int          g_deg[NN];
__device__ float        g_dinv[NN];
__device__ float4       g_xt[NN * 2];    // x[b, T-1, n] transposed to [n][8] (fp32)
__device__ uint4        g_gth[NN];       // dinv[n] * xt[n][b], packed 8 x f16
__device__ uint4        g_acch[NN];      // scatter accumulator, 8 x f16 per node
__device__ float        g_bsum[NB * NH]; // per-(b,h) node sums
__device__ unsigned int g_cnt;

// ---------------------------------------------------------------------------
__device__ __forceinline__ float tanh_fast(float x) {
    float y;
    asm("tanh.approx.f32 %0, %1;" : "=f"(y) : "f"(x));
    return y;
}

__device__ __forceinline__ void red_add_v4h2(uint4* addr, uint4 v) {
    asm volatile("red.global.add.noftz.v4.f16x2 [%0], {%1, %2, %3, %4};"
                 :: "l"(addr), "r"(v.x), "r"(v.y), "r"(v.z), "r"(v.w)
                 : "memory");
}

// ---------------------------------------------------------------------------
// K1: degree histogram (src column) + transpose last-timestep x to [n][8]
__global__ void k_deg_xt(const int* __restrict__ ei, const float* __restrict__ x) {
    int i = blockIdx.x * blockDim.x + threadIdx.x;
    int stride = gridDim.x * blockDim.x;

    const int4* s4 = (const int4*)ei;  // src = ei[0..EE)
    for (int j = i; j < EE / 4; j += stride) {
        int4 s = __ldcs(&s4[j]);
        atomicAdd(&g_deg[s.x], 1);
        atomicAdd(&g_deg[s.y], 1);
        atomicAdd(&g_deg[s.z], 1);
        atomicAdd(&g_deg[s.w], 1);
    }

    // x layout: [B, T, N]; take t = T-1 slice for each b (stride-1 in n -> coalesced)
    const float* xl = x + (TT - 1) * NN;
    for (int n = i; n < NN; n += stride) {
        float4 a, b;
        a.x = xl[0 * TT * NN + n];
        a.y = xl[1 * TT * NN + n];
        a.z = xl[2 * TT * NN + n];
        a.w = xl[3 * TT * NN + n];
        g_xt[2 * n] = a;
        b.x = xl[4 * TT * NN + n];
        b.y = xl[5 * TT * NN + n];
        b.z = xl[6 * TT * NN + n];
        b.w = xl[7 * TT * NN + n];
        g_xt[2 * n + 1] = b;
    }
}

// ---------------------------------------------------------------------------
// K2: dinv = rsqrt(deg); gth = f16(dinv * xt); zero acch + bsum + cnt
__global__ void k_dinv() {
    int i = blockIdx.x * blockDim.x + threadIdx.x;
    int stride = gridDim.x * blockDim.x;
    uint4 z4 = make_uint4(0u, 0u, 0u, 0u);
    for (int n = i; n < NN; n += stride) {
        int d = g_deg[n];
        float dv = (d > 0) ? rsqrtf((float)d) : 0.f;
        g_dinv[n] = dv;
        float4 a = g_xt[2 * n];
        float4 b = g_xt[2 * n + 1];
        __half2 h0 = __floats2half2_rn(a.x * dv, a.y * dv);
        __half2 h1 = __floats2half2_rn(a.z * dv, a.w * dv);
        __half2 h2 = __floats2half2_rn(b.x * dv, b.y * dv);
        __half2 h3 = __floats2half2_rn(b.z * dv, b.w * dv);
        uint4 p;
        p.x = *(unsigned int*)&h0;
        p.y = *(unsigned int*)&h1;
        p.z = *(unsigned int*)&h2;
        p.w = *(unsigned int*)&h3;
        g_gth[n] = p;
        g_acch[n] = z4;
    }
    if (i < NB * NH) g_bsum[i] = 0.f;
    if (i == 0) g_cnt = 0u;
}

// ---------------------------------------------------------------------------
// K3: main edge scatter: acc[dst][0..7] += gt[src][0..7] via one 16B f16x2 RED
__global__ void k_scatter(const int* __restrict__ ei) {
    int i = blockIdx.x * blockDim.x + threadIdx.x;
    int stride = gridDim.x * blockDim.x;
    const int4* s4 = (const int4*)ei;         // src
    const int4* d4 = (const int4*)(ei + EE);  // dst
    for (int j = i; j < EE / 4; j += stride) {
        int4 s = __ldcs(&s4[j]);
        int4 d = __ldcs(&d4[j]);
        uint4 a0 = __ldg(&g_gth[s.x]);
        uint4 a1 = __ldg(&g_gth[s.y]);
        uint4 a2 = __ldg(&g_gth[s.z]);
        uint4 a3 = __ldg(&g_gth[s.w]);
        red_add_v4h2(&g_acch[d.x], a0);
        red_add_v4h2(&g_acch[d.y], a1);
        red_add_v4h2(&g_acch[d.z], a2);
        red_add_v4h2(&g_acch[d.w], a3);
    }
}

// ---------------------------------------------------------------------------
// K4: gate math + reduction. 4 hidden units per thread, fp32 math + fp32 accum.
// Warp map: slot = lane>>2 (== batch b, hoisted), hg = (lane&3)*4.
// Pointer-increment loop with exact trip count + unroll 4 -> front-batched loads.
__global__ void __launch_bounds__(256)
k_combine(const float* __restrict__ wxz, const float* __restrict__ bxz,
          const float* __restrict__ bhz, const float* __restrict__ wxh,
          const float* __restrict__ bxh, const float* __restrict__ bhh,
          const float* __restrict__ wlin, const float* __restrict__ blin,
          float* __restrict__ out) {
    const int t    = threadIdx.x;
    const int lane = t & 31;
    const int slot = lane >> 2;            // 0..7 == batch b (invariant)
    const int hg   = (lane & 3) * 4;       // h base: 0,4,8,12

    // Stage weights in smem once per block (z-side pre-halved for tanh(za/2))
    __shared__ float swz0[NH], swz1[NH], sbz[NH], swh0[NH], swh1[NH], sbh[NH];
    if (t < NH) {
        swz0[t] = 0.5f * wxz[t];
        swz1[t] = 0.5f * wxz[NH + t];
        sbz[t]  = 0.5f * (bxz[t] + bhz[t]);
        swh0[t] = wxh[t];
        swh1[t] = wxh[NH + t];
        sbh[t]  = bxh[t] + bhh[t];
    }
    __syncthreads();

    float w0z[4], w1z[4], bz[4], w0h[4], w1h[4], bh[4];
#pragma unroll
    for (int j = 0; j < 4; j++) {
        w0z[j] = swz0[hg + j];  w1z[j] = swz1[hg + j];  bz[j] = sbz[hg + j];
        w0h[j] = swh0[hg + j];  w1h[j] = swh1[hg + j];  bh[j] = sbh[hg + j];
    }

    const int warp_g      = (blockIdx.x * blockDim.x + t) >> 5;
    const int total_warps = (gridDim.x * blockDim.x) >> 5;   // 4736
    const int stride_idx  = total_warps * 8;                 // 37888, multiple of 8
    const int start       = warp_g * 8 + slot;               // < 37888 -> >=1 iter
    const int n_iter      = (NN * NB - 1 - start) / stride_idx + 1;  // 10 or 11

    const float*  p_x = (const float*)g_xt + start;
    const __half* p_a = (const __half*)g_acch + start;
    const float*  p_d = g_dinv + (start >> 3);
    const int     dstep = stride_idx >> 3;

    float acc[4] = {0.f, 0.f, 0.f, 0.f};
#pragma unroll 4
    for (int it = 0; it < n_iter; ++it) {
        float xv  = *p_x;
        float av  = __half2float(*p_a);
        float dv  = *p_d;
        p_x += stride_idx;  p_a += stride_idx;  p_d += dstep;
        float lxv = -dv * av;
#pragma unroll
        for (int j = 0; j < 4; j++) {
            float u = fmaf(xv, w0z[j], fmaf(lxv, w1z[j], bz[j]));
            float a = fmaf(xv, w0h[j], fmaf(lxv, w1h[j], bh[j]));
            // (1 - sigmoid(2u)) * tanh(a) = (0.5 - 0.5*tanh(u)) * tanh(a)
            acc[j] += fmaf(-0.5f, tanh_fast(u), 0.5f) * tanh_fast(a);
        }
    }

    __shared__ float sbsum[NB * NH];
    if (t < NB * NH) sbsum[t] = 0.f;
    __syncthreads();
#pragma unroll
    for (int j = 0; j < 4; j++) atomicAdd(&sbsum[slot * NH + hg + j], acc[j]);
    __syncthreads();

    if (t < NB * NH) atomicAdd(&g_bsum[t], sbsum[t]);
    __syncthreads();

    __shared__ unsigned int s_last;
    if (t == 0) {
        __threadfence();
        s_last = (atomicAdd(&g_cnt, 1u) == gridDim.x - 1) ? 1u : 0u;
    }
    __syncthreads();

    if (s_last && t < NB) {
        const float inv_n = 1.f / (float)NN;
        float s = 0.f;
#pragma unroll
        for (int h = 0; h < NH; h++) {
            float m = __ldcg(&g_bsum[t * NH + h]) * inv_n;
            s += fmaxf(m, 0.f) * wlin[h];
        }
        out[t] = s + blin[0];
    }
}

// ---------------------------------------------------------------------------
extern "C" void kernel_launch(void* const* d_in, const int* in_sizes, int n_in,
                              void* d_out, int out_size) {
    const float* x    = (const float*)d_in[0];  // [B,T,N,1]
    const int*   ei   = (const int*)d_in[1];    // [2,E]
    const float* wxz  = (const float*)d_in[2];  // [2,16]
    const float* bxz  = (const float*)d_in[3];
    const float* bhz  = (const float*)d_in[4];
    const float* wxh  = (const float*)d_in[5];
    const float* bxh  = (const float*)d_in[6];
    const float* bhh  = (const float*)d_in[7];
    const float* wlin = (const float*)d_in[8];  // [1,16]
    const float* blin = (const float*)d_in[9];  // [1]
    float* out = (float*)d_out;                 // [8]

    // zero g_deg via a graph memset node
    void* p_deg = nullptr;
    cudaGetSymbolAddress(&p_deg, g_deg);
    cudaMemsetAsync(p_deg, 0, NN * sizeof(int));

    k_deg_xt<<<1184, 256>>>(ei, x);
    k_dinv<<<296, 256>>>();
    k_scatter<<<1184, 256>>>(ei);
    k_combine<<<592, 256>>>(wxz, bxz, bhz, wxh, bxh, bhh, wlin, blin, out);
}